// round 10
// baseline (speedup 1.0000x reference)
#include <cuda_runtime.h>
#include <cuda_bf16.h>

// MoE routing histogram, single fused kernel (float32 harness buffers).
//
// R10 = R9 with the macro-shadowing compile fix (macro locals prefixed).
//  - MLP x4: four independent int4 loads per grid-stride iteration.
//  - BINADE FAST PATH: when the affine window [off, off+n) sits in a single
//    float binade, bin = (bits - base_bits) >> sh with an exact unsigned
//    range check -- no F2I cvt, pure fast-ALU ops.
//  - __ldcs streaming loads (no reuse -> evict-first).
// Retained: dtype sniff (int fallback), LUT fallback, 8x per-warp replicated
// shared histograms, global-atomic partials, last-block finalize + scratch
// re-zero (graph-replay safe).

#define NB        1184     // 148 SMs * 8 CTAs
#define TPB       256
#define NWARPS    (TPB / 32)
#define MAX_BINS  256
#define BIN_PAD   (MAX_BINS + 1)
#define MAX_MAP   512

__device__ int g_counts[MAX_BINS];
__device__ unsigned g_done;

__global__ __launch_bounds__(TPB) void hist_kernel(
    const int* __restrict__ ids, long long n,
    const int* __restrict__ emap, int map_n, int n_local,
    float* __restrict__ out, int out_elems)
{
    __shared__ int s_map[MAX_MAP];
    __shared__ int s_hist[NWARPS][BIN_PAD];
    __shared__ int s_ids_int_ok, s_map_int_ok, s_affine, s_off;

    const int tid = threadIdx.x;

    // ---- dtype sniff ----
    if (tid == 0) { s_ids_int_ok = 1; s_map_int_ok = 1; s_affine = 1; s_off = 0x7FFFFFFF; }
    __syncthreads();
    if (tid < 256 && (long long)tid < n) {
        if ((unsigned)ids[tid] >= 65536u) atomicAnd(&s_ids_int_ok, 0);
    }
    if (emap != nullptr && tid < map_n) {
        unsigned w = (unsigned)emap[tid];
        if (w >= 65536u && w != 0xFFFFFFFFu) atomicAnd(&s_map_int_ok, 0);
    }
    __syncthreads();
    const int ids_float = !s_ids_int_ok;
    const int map_float = !s_map_int_ok;

    // ---- build LUT in int space ----
    int eff_map_n = map_n;
    if (emap != nullptr && map_n > 0) {
        if (map_float) {
            const float* mf = (const float*)emap;
            for (int i = tid; i < map_n; i += TPB) {
                float v = mf[i];
                s_map[i] = (v >= 0.0f && v < (float)MAX_BINS) ? (int)v : -1;
            }
        } else {
            for (int i = tid; i < map_n; i += TPB) s_map[i] = emap[i];
        }
    } else {
        eff_map_n = MAX_MAP;
        for (int i = tid; i < MAX_MAP; i += TPB) s_map[i] = (i < n_local) ? i : -1;
    }
    for (int i = tid; i < NWARPS * BIN_PAD; i += TPB) (&s_hist[0][0])[i] = 0;
    __syncthreads();

    // ---- affine detection: s_map[i] == ((unsigned)(i-off)<un ? i-off : -1) --
    const unsigned un = (unsigned)n_local;
    for (int i = tid; i < eff_map_n; i += TPB)
        if (s_map[i] >= 0) atomicMin(&s_off, i - s_map[i]);
    __syncthreads();
    const int off = s_off;
    for (int i = tid; i < eff_map_n; i += TPB) {
        int expect = ((unsigned)(i - off) < un) ? (i - off) : -1;
        if (s_map[i] != expect) atomicAnd(&s_affine, 0);
    }
    __syncthreads();
    const int affine = s_affine && (off != 0x7FFFFFFF) && (off >= 0) &&
                       (off + (int)un <= eff_map_n);

    // ---- binade fast-path constants (float ids, affine window inside one
    //      power-of-two binade [2^e, 2^{e+1})) ----
    int binade = 0; unsigned base_bits = 0, span = 0; int sh = 0;
    if (affine && ids_float && off > 0 && (int)un > 0) {
        int e_lo = 31 - __clz(off);
        int e_hi = 31 - __clz(off + (int)un - 1);
        if (e_lo == e_hi && e_lo <= 23) {
            binade    = 1;
            sh        = 23 - e_lo;
            base_bits = __float_as_uint((float)off);
            span      = un << sh;
        }
    }

    int* hist = s_hist[tid >> 5];
    const unsigned um = (unsigned)eff_map_n;
    const float off_f = (float)off;
    const long long st = (long long)NB * TPB;

#define PROC_BIN(W)                                                     \
    {                                                                   \
        unsigned _d = (unsigned)(W) - base_bits;                        \
        if (_d < span) atomicAdd(&hist[_d >> sh], 1);                   \
    }
#define PROC_F_AFF(W)                                                   \
    {                                                                   \
        int _m = (int)(__int_as_float(W) - off_f);                      \
        if ((unsigned)_m < un) atomicAdd(&hist[_m], 1);                 \
    }
#define PROC_F_LUT(W)                                                   \
    {                                                                   \
        unsigned _idx = (unsigned)(int)__int_as_float(W);               \
        int _m = (_idx < um) ? s_map[_idx] : -1;                        \
        if ((unsigned)_m < un) atomicAdd(&hist[_m], 1);                 \
    }
#define PROC_I_AFF(W)                                                   \
    {                                                                   \
        int _m = (W) - off;                                             \
        if ((unsigned)_m < un) atomicAdd(&hist[_m], 1);                 \
    }
#define PROC_I_LUT(W)                                                   \
    {                                                                   \
        unsigned _idx = (unsigned)(W);                                  \
        int _m = (_idx < um) ? s_map[_idx] : -1;                        \
        if ((unsigned)_m < un) atomicAdd(&hist[_m], 1);                 \
    }

    const int4* __restrict__ v = (const int4*)ids;
    const long long n4 = n >> 2;
    long long i = (long long)blockIdx.x * TPB + tid;

    if (binade) {
        // MLP x4 main loop.
        for (; i + 3 * st < n4; i += 4 * st) {
            int4 va = __ldcs(&v[i]);
            int4 vb = __ldcs(&v[i + st]);
            int4 vc = __ldcs(&v[i + 2 * st]);
            int4 vd = __ldcs(&v[i + 3 * st]);
            PROC_BIN(va.x); PROC_BIN(va.y); PROC_BIN(va.z); PROC_BIN(va.w);
            PROC_BIN(vb.x); PROC_BIN(vb.y); PROC_BIN(vb.z); PROC_BIN(vb.w);
            PROC_BIN(vc.x); PROC_BIN(vc.y); PROC_BIN(vc.z); PROC_BIN(vc.w);
            PROC_BIN(vd.x); PROC_BIN(vd.y); PROC_BIN(vd.z); PROC_BIN(vd.w);
        }
        for (; i < n4; i += st) {
            int4 va = __ldcs(&v[i]);
            PROC_BIN(va.x); PROC_BIN(va.y); PROC_BIN(va.z); PROC_BIN(va.w);
        }
        if (blockIdx.x == 0)
            for (long long j = (n4 << 2) + tid; j < n; j += TPB) PROC_BIN(ids[j]);
    } else if (ids_float && affine) {
        for (; i + st < n4; i += 2 * st) {
            int4 va = __ldcs(&v[i]);
            int4 vb = __ldcs(&v[i + st]);
            PROC_F_AFF(va.x); PROC_F_AFF(va.y); PROC_F_AFF(va.z); PROC_F_AFF(va.w);
            PROC_F_AFF(vb.x); PROC_F_AFF(vb.y); PROC_F_AFF(vb.z); PROC_F_AFF(vb.w);
        }
        for (; i < n4; i += st) {
            int4 va = __ldcs(&v[i]);
            PROC_F_AFF(va.x); PROC_F_AFF(va.y); PROC_F_AFF(va.z); PROC_F_AFF(va.w);
        }
        if (blockIdx.x == 0)
            for (long long j = (n4 << 2) + tid; j < n; j += TPB) PROC_F_AFF(ids[j]);
    } else if (ids_float) {
        for (; i + st < n4; i += 2 * st) {
            int4 va = __ldcs(&v[i]);
            int4 vb = __ldcs(&v[i + st]);
            PROC_F_LUT(va.x); PROC_F_LUT(va.y); PROC_F_LUT(va.z); PROC_F_LUT(va.w);
            PROC_F_LUT(vb.x); PROC_F_LUT(vb.y); PROC_F_LUT(vb.z); PROC_F_LUT(vb.w);
        }
        for (; i < n4; i += st) {
            int4 va = __ldcs(&v[i]);
            PROC_F_LUT(va.x); PROC_F_LUT(va.y); PROC_F_LUT(va.z); PROC_F_LUT(va.w);
        }
        if (blockIdx.x == 0)
            for (long long j = (n4 << 2) + tid; j < n; j += TPB) PROC_F_LUT(ids[j]);
    } else if (affine) {
        for (; i + st < n4; i += 2 * st) {
            int4 va = __ldcs(&v[i]);
            int4 vb = __ldcs(&v[i + st]);
            PROC_I_AFF(va.x); PROC_I_AFF(va.y); PROC_I_AFF(va.z); PROC_I_AFF(va.w);
            PROC_I_AFF(vb.x); PROC_I_AFF(vb.y); PROC_I_AFF(vb.z); PROC_I_AFF(vb.w);
        }
        for (; i < n4; i += st) {
            int4 va = __ldcs(&v[i]);
            PROC_I_AFF(va.x); PROC_I_AFF(va.y); PROC_I_AFF(va.z); PROC_I_AFF(va.w);
        }
        if (blockIdx.x == 0)
            for (long long j = (n4 << 2) + tid; j < n; j += TPB) PROC_I_AFF(ids[j]);
    } else {
        for (; i + st < n4; i += 2 * st) {
            int4 va = __ldcs(&v[i]);
            int4 vb = __ldcs(&v[i + st]);
            PROC_I_LUT(va.x); PROC_I_LUT(va.y); PROC_I_LUT(va.z); PROC_I_LUT(va.w);
            PROC_I_LUT(vb.x); PROC_I_LUT(vb.y); PROC_I_LUT(vb.z); PROC_I_LUT(vb.w);
        }
        for (; i < n4; i += st) {
            int4 va = __ldcs(&v[i]);
            PROC_I_LUT(va.x); PROC_I_LUT(va.y); PROC_I_LUT(va.z); PROC_I_LUT(va.w);
        }
        if (blockIdx.x == 0)
            for (long long j = (n4 << 2) + tid; j < n; j += TPB) PROC_I_LUT(ids[j]);
    }
#undef PROC_BIN
#undef PROC_F_AFF
#undef PROC_F_LUT
#undef PROC_I_AFF
#undef PROC_I_LUT

    __syncthreads();

    // ---- collapse replicas -> deterministic global partials ----
    for (int b = tid; b < n_local; b += TPB) {
        int s = 0;
#pragma unroll
        for (int r = 0; r < NWARPS; r++) s += s_hist[r][b];
        if (s) atomicAdd(&g_counts[b], s);
    }

    // ---- last-block finalize ----
    __threadfence();
    __shared__ unsigned s_rank;
    if (tid == 0) s_rank = atomicAdd(&g_done, 1u);
    __syncthreads();

    if (s_rank == NB - 1) {
        for (int b = tid; b < out_elems; b += TPB)
            out[b] = (b < n_local) ? (float)g_counts[b] : 0.0f;
        __syncthreads();
        for (int b = tid; b < MAX_BINS; b += TPB) g_counts[b] = 0;
        if (tid == 0) g_done = 0u;
    }
}

extern "C" void kernel_launch(void* const* d_in, const int* in_sizes, int n_in,
                              void* d_out, int out_size)
{
    int imax = 0;
    for (int i = 1; i < n_in; i++)
        if (in_sizes[i] > in_sizes[imax]) imax = i;

    const int* ids = (const int*)d_in[imax];
    long long n    = (long long)in_sizes[imax];

    const int* emap = nullptr;
    int map_n = 0;
    for (int i = 0; i < n_in; i++) {
        if (i == imax) continue;
        if (in_sizes[i] > 1 && in_sizes[i] <= MAX_MAP && in_sizes[i] > map_n) {
            emap  = (const int*)d_in[i];
            map_n = in_sizes[i];
        }
    }

    int n_local = out_size;
    if (n_local > MAX_BINS) n_local = MAX_BINS;
    if (n_local < 1) n_local = 1;

    hist_kernel<<<NB, TPB>>>(ids, n, emap, map_n, n_local,
                             (float*)d_out, out_size);
}